// round 1
// baseline (speedup 1.0000x reference)
#include <cuda_runtime.h>

#define OMEGA0 30.0f
#define BLK 128
#define IT 4

// ---------- packed f32x2 FMA (sm_103a FFMA2, only reachable via PTX) ----------
union F2u { float2 f; unsigned long long u; };

__device__ __forceinline__ float2 ffma2(float2 a, float2 b, float2 c) {
    F2u A, B, C, D;
    A.f = a; B.f = b; C.f = c;
    asm("fma.rn.f32x2 %0, %1, %2, %3;" : "=l"(D.u) : "l"(A.u), "l"(B.u), "l"(C.u));
    return D.f;
}

// ---------- sine with cheap Cody-Waite reduction, then MUFU.SIN ----------
__device__ __forceinline__ float fast_sin(float t) {
    float k = rintf(t * 0.15915494309189535f);      // t / (2*pi)
    t = fmaf(k, -6.2831854820251465f, t);           // hi word of 2*pi
    t = fmaf(k,  1.7484556e-7f,       t);           // -(2*pi - hi)
    return __sinf(t);
}

__device__ __forceinline__ float fast_sigmoid(float t) {
    float e = __expf(-t);
    return __fdividef(1.0f, 1.0f + e);
}

// ---------- one 32->32 sine layer for 2 points, k packed in f32x2 pairs ----------
__device__ __forceinline__ void mid_layer(
    const float* __restrict__ sw,   // 32x32 row-major, prescaled by omega0
    const float* __restrict__ sb,   // 32, prescaled
    const float2* xa, const float2* xb,   // in: 16 packed pairs per point
    float2* ya, float2* yb)                // out: 16 packed pairs per point
{
#pragma unroll
    for (int j = 0; j < 32; j++) {
        const float4* w4 = (const float4*)(sw + j * 32);
        float bj = sb[j];
        float2 a0 = make_float2(bj, 0.0f);
        float2 a1 = make_float2(bj, 0.0f);
#pragma unroll
        for (int m = 0; m < 8; m++) {
            float4 w = w4[m];
            float2 wlo = make_float2(w.x, w.y);
            float2 whi = make_float2(w.z, w.w);
            a0 = ffma2(xa[2 * m],     wlo, a0);
            a1 = ffma2(xb[2 * m],     wlo, a1);
            a0 = ffma2(xa[2 * m + 1], whi, a0);
            a1 = ffma2(xb[2 * m + 1], whi, a1);
        }
        float sa = fast_sin(a0.x + a0.y);
        float sb_ = fast_sin(a1.x + a1.y);
        if (j & 1) { ya[j >> 1].y = sa; yb[j >> 1].y = sb_; }
        else       { ya[j >> 1].x = sa; yb[j >> 1].x = sb_; }
    }
}

__global__ void __launch_bounds__(BLK)
siren_kernel(const float* __restrict__ coords,
             const float* __restrict__ w0g, const float* __restrict__ b0g,
             const float* __restrict__ w1g, const float* __restrict__ b1g,
             const float* __restrict__ w2g, const float* __restrict__ b2g,
             const float* __restrict__ w3g, const float* __restrict__ b3g,
             const float* __restrict__ w4g, const float* __restrict__ b4g,
             const float* __restrict__ w5g, const float* __restrict__ b5g,
             const float* __restrict__ wfg, const float* __restrict__ bfg,
             float* __restrict__ out, int numPairs)
{
    __shared__ __align__(16) float s_w0[64];
    __shared__              float s_b0[32];
    __shared__ __align__(16) float s_wm[4 * 1024];
    __shared__              float s_bm[4 * 32];
    __shared__ __align__(16) float s_w5[512];
    __shared__              float s_b5[16];
    __shared__ __align__(16) float s_wf[48];
    __shared__              float s_bf[3];

    const int t = threadIdx.x;
    for (int i = t; i < 64; i += BLK)  s_w0[i] = OMEGA0 * w0g[i];
    for (int i = t; i < 32; i += BLK)  s_b0[i] = OMEGA0 * b0g[i];
    {
        const float* wml[4] = { w1g, w2g, w3g, w4g };
        const float* bml[4] = { b1g, b2g, b3g, b4g };
#pragma unroll
        for (int l = 0; l < 4; l++) {
            for (int i = t; i < 1024; i += BLK) s_wm[l * 1024 + i] = OMEGA0 * wml[l][i];
            for (int i = t; i < 32;   i += BLK) s_bm[l * 32 + i]   = OMEGA0 * bml[l][i];
        }
    }
    for (int i = t; i < 512; i += BLK) s_w5[i] = OMEGA0 * w5g[i];
    for (int i = t; i < 16;  i += BLK) s_b5[i] = OMEGA0 * b5g[i];
    for (int i = t; i < 48;  i += BLK) s_wf[i] = wfg[i];
    for (int i = t; i < 3;   i += BLK) s_bf[i] = bfg[i];
    __syncthreads();

    const int base = blockIdx.x * (BLK * IT);

#pragma unroll 1
    for (int it = 0; it < IT; it++) {
        const int pair = base + it * BLK + t;
        if (pair >= numPairs) break;

        // ---- load 2 points (float4 = 2 x (x,y)) ----
        float4 c4 = ((const float4*)coords)[pair];
        float2 p0 = make_float2(c4.x, c4.y);
        float2 p1 = make_float2(c4.z, c4.w);

        float2 xa[16], xb[16];
        float2 ya[16], yb[16];

        // ---- layer 0: 2 -> 32 ----
#pragma unroll
        for (int j = 0; j < 32; j++) {
            float2 w = ((const float2*)s_w0)[j];
            float2 a0 = make_float2(s_b0[j], 0.0f);
            float2 a1 = a0;
            a0 = ffma2(p0, w, a0);
            a1 = ffma2(p1, w, a1);
            float sa = fast_sin(a0.x + a0.y);
            float sb_ = fast_sin(a1.x + a1.y);
            if (j & 1) { xa[j >> 1].y = sa; xb[j >> 1].y = sb_; }
            else       { xa[j >> 1].x = sa; xb[j >> 1].x = sb_; }
        }

        // ---- 4 middle layers 32 -> 32 (ping-pong x <-> y) ----
#pragma unroll 1
        for (int l = 0; l < 2; l++) {
            mid_layer(s_wm + (2 * l)     * 1024, s_bm + (2 * l)     * 32, xa, xb, ya, yb);
            mid_layer(s_wm + (2 * l + 1) * 1024, s_bm + (2 * l + 1) * 32, ya, yb, xa, xb);
        }

        // ---- layer 5: 32 -> 16 ----
        float2 za[8], zb[8];
#pragma unroll
        for (int j = 0; j < 16; j++) {
            const float4* w4 = (const float4*)(s_w5 + j * 32);
            float bj = s_b5[j];
            float2 a0 = make_float2(bj, 0.0f);
            float2 a1 = make_float2(bj, 0.0f);
#pragma unroll
            for (int m = 0; m < 8; m++) {
                float4 w = w4[m];
                float2 wlo = make_float2(w.x, w.y);
                float2 whi = make_float2(w.z, w.w);
                a0 = ffma2(xa[2 * m],     wlo, a0);
                a1 = ffma2(xb[2 * m],     wlo, a1);
                a0 = ffma2(xa[2 * m + 1], whi, a0);
                a1 = ffma2(xb[2 * m + 1], whi, a1);
            }
            float sa = fast_sin(a0.x + a0.y);
            float sb_ = fast_sin(a1.x + a1.y);
            if (j & 1) { za[j >> 1].y = sa; zb[j >> 1].y = sb_; }
            else       { za[j >> 1].x = sa; zb[j >> 1].x = sb_; }
        }

        // ---- final layer: 16 -> 3 + sigmoid ----
        float o0[3], o1[3];
#pragma unroll
        for (int c = 0; c < 3; c++) {
            const float4* w4 = (const float4*)(s_wf + c * 16);
            float2 a0 = make_float2(s_bf[c], 0.0f);
            float2 a1 = a0;
#pragma unroll
            for (int m = 0; m < 4; m++) {
                float4 w = w4[m];
                float2 wlo = make_float2(w.x, w.y);
                float2 whi = make_float2(w.z, w.w);
                a0 = ffma2(za[2 * m],     wlo, a0);
                a1 = ffma2(zb[2 * m],     wlo, a1);
                a0 = ffma2(za[2 * m + 1], whi, a0);
                a1 = ffma2(zb[2 * m + 1], whi, a1);
            }
            o0[c] = fast_sigmoid(a0.x + a0.y);
            o1[c] = fast_sigmoid(a1.x + a1.y);
        }

        // ---- store 6 floats (2 points x RGB) as 3x STG.64 ----
        float2* op = (float2*)(out + (size_t)pair * 6);
        op[0] = make_float2(o0[0], o0[1]);
        op[1] = make_float2(o0[2], o1[0]);
        op[2] = make_float2(o1[1], o1[2]);
    }
}

extern "C" void kernel_launch(void* const* d_in, const int* in_sizes, int n_in,
                              void* d_out, int out_size)
{
    const float* coords = (const float*)d_in[0];
    const float* w0 = (const float*)d_in[1];  const float* b0 = (const float*)d_in[2];
    const float* w1 = (const float*)d_in[3];  const float* b1 = (const float*)d_in[4];
    const float* w2 = (const float*)d_in[5];  const float* b2 = (const float*)d_in[6];
    const float* w3 = (const float*)d_in[7];  const float* b3 = (const float*)d_in[8];
    const float* w4 = (const float*)d_in[9];  const float* b4 = (const float*)d_in[10];
    const float* w5 = (const float*)d_in[11]; const float* b5 = (const float*)d_in[12];
    const float* wf = (const float*)d_in[13]; const float* bf = (const float*)d_in[14];

    int numPairs = in_sizes[0] / 4;                 // coords has N*2 floats, 2 points per pair
    int pairsPerBlock = BLK * IT;
    int grid = (numPairs + pairsPerBlock - 1) / pairsPerBlock;

    siren_kernel<<<grid, BLK>>>(coords, w0, b0, w1, b1, w2, b2, w3, b3, w4, b4,
                                w5, b5, wf, bf, (float*)d_out, numPairs);
}